// round 12
// baseline (speedup 1.0000x reference)
#include <cuda_runtime.h>
#include <cuda_bf16.h>
#include <cstdint>

// Problem constants
#define NIMG 16
#define CIN 128
#define HDIM 64
#define WDIM 64
#define BTOT (NIMG*WDIM)      // 1024
#define OQKV 256
#define NGROUP 8
#define BNEPS 1e-5f

// ---------------- scratch ----------------
__device__ __align__(16) float g_xt [BTOT * CIN * HDIM];     // [b][c][h]
__device__ __align__(16) float g_qkv[BTOT * OQKV * HDIM];    // [b][o][h]
__device__ __align__(16) float g_att[BTOT * 128 * HDIM];     // [b][p][h]
__device__ __align__(16) __nv_bfloat16 g_whi[OQKV * CIN];
__device__ __align__(16) __nv_bfloat16 g_wlo[OQKV * CIN];
__device__ float g_bias[OQKV];
__device__ float g_sc  [OQKV];
__device__ float g_aqk[NGROUP], g_aqr[NGROUP], g_akr[NGROUP];
__device__ float g_ae[128], g_ao[128], g_bs[128];

// ---------------- mma.sync helpers (sm_80+ PTX) ------------------------------
__device__ __forceinline__ uint32_t smem_u32(const void* p) {
    uint32_t a;
    asm("{ .reg .u64 t; cvta.to.shared.u64 t, %1; cvt.u32.u64 %0, t; }" : "=r"(a) : "l"(p));
    return a;
}
__device__ __forceinline__ void ldsm_x4(uint32_t* r, uint32_t addr) {
    asm volatile("ldmatrix.sync.aligned.m8n8.x4.shared.b16 {%0,%1,%2,%3}, [%4];"
                 : "=r"(r[0]), "=r"(r[1]), "=r"(r[2]), "=r"(r[3]) : "r"(addr));
}
__device__ __forceinline__ void mma_bf16(float* c, const uint32_t* a, const uint32_t* b) {
    asm volatile("mma.sync.aligned.m16n8k16.row.col.f32.bf16.bf16.f32 "
                 "{%0,%1,%2,%3}, {%4,%5,%6,%7}, {%8,%9}, {%0,%1,%2,%3};"
                 : "+f"(c[0]), "+f"(c[1]), "+f"(c[2]), "+f"(c[3])
                 : "r"(a[0]), "r"(a[1]), "r"(a[2]), "r"(a[3]), "r"(b[0]), "r"(b[1]));
}
__device__ __forceinline__ void bsplit(float v, __nv_bfloat16& hi, __nv_bfloat16& lo) {
    hi = __float2bfloat16_rn(v);
    lo = __float2bfloat16_rn(v - __bfloat162float(hi));
}

// ---------------- prep ----------------
__global__ void prep_params(const float* __restrict__ bnq,
                            const float* __restrict__ bns,
                            const float* __restrict__ bno) {
    int t = threadIdx.x;
    if (t < 256) {
        float ga = bnq[t], be = bnq[256 + t], m = bnq[512 + t], v = bnq[768 + t];
        float s = ga * rsqrtf(v + BNEPS);
        g_sc[t]  = s;
        g_bias[t] = be - s * m;
    }
    if (t < 24) {
        float s = bns[t] * rsqrtf(bns[72 + t] + BNEPS);
        if (t < 8)       g_aqk[t]      = s;
        else if (t < 16) g_aqr[t - 8]  = s;
        else             g_akr[t - 16] = s;
    }
    if (t < 128) {
        int c0 = 2 * t, c1 = 2 * t + 1;
        float s0 = bno[c0] * rsqrtf(bno[768 + c0] + BNEPS);
        float s1 = bno[c1] * rsqrtf(bno[768 + c1] + BNEPS);
        g_ae[t] = s0;
        g_ao[t] = s1;
        g_bs[t] = (bno[256 + c0] - s0 * bno[512 + c0])
                + (bno[256 + c1] - s1 * bno[512 + c1]);
    }
}

__global__ void prep_wsplit(const float* __restrict__ w) {
    int o = blockIdx.x, k = threadIdx.x;
    float we = w[o * 128 + k] * g_sc[o];
    __nv_bfloat16 hi, lo;
    bsplit(we, hi, lo);
    g_whi[o * 128 + k] = hi;
    g_wlo[o * 128 + k] = lo;
}

// ---------------- transpose x ----------------
__global__ void tr_x(const float* __restrict__ x) {
    __shared__ float tile[32][33];
    int nc = blockIdx.z;
    int n = nc >> 7, c = nc & 127;
    int h0 = blockIdx.x * 32, w0 = blockIdx.y * 32;
    const float* src = x + ((size_t)(n * 128 + c)) * 4096;
    #pragma unroll
    for (int y = threadIdx.y; y < 32; y += 8)
        tile[y][threadIdx.x] = src[(h0 + y) * 64 + w0 + threadIdx.x];
    __syncthreads();
    #pragma unroll
    for (int y = threadIdx.y; y < 32; y += 8)
        g_xt[((size_t)((n * 64 + (w0 + y)) * 128 + c)) * 64 + h0 + threadIdx.x]
            = tile[threadIdx.x][y];
}

// ---------------- QKV GEMM (unchanged from R11 pass) ----------------
#define LDW 136
#define SM_WHI 0
#define SM_WLO (SM_WHI + OQKV * LDW * 2)
#define SM_XHI (SM_WLO + OQKV * LDW * 2)
#define SM_XLO (SM_XHI + HDIM * LDW * 2)
#define SM_TOTAL (SM_XLO + HDIM * LDW * 2)

__global__ void __launch_bounds__(256, 1) qkv_mma() {
    extern __shared__ __align__(16) char smem[];
    uint32_t sb = smem_u32(smem);
    int t = threadIdx.x;
    int wid = t >> 5, lane = t & 31;

    {
        const float4* whi = (const float4*)g_whi;
        const float4* wlo = (const float4*)g_wlo;
        #pragma unroll
        for (int i = 0; i < 16; i++) {
            int idx = t + i * 256;
            int o = idx >> 4, c4 = idx & 15;
            *(float4*)(smem + SM_WHI + o * (LDW * 2) + c4 * 16) = whi[idx];
            *(float4*)(smem + SM_WLO + o * (LDW * 2) + c4 * 16) = wlo[idx];
        }
    }

    uint32_t a_row = (uint32_t)(wid * 32) + (lane & 15);
    uint32_t a_off = a_row * (LDW * 2) + ((lane >> 4) << 3) * 2;
    uint32_t b_row = ((lane >> 4) << 3) + (lane & 7);
    uint32_t b_off = b_row * (LDW * 2) + (((lane >> 3) & 1) << 3) * 2;

    float bias_lo[2], bias_hi[2];
    #pragma unroll
    for (int mt = 0; mt < 2; mt++) {
        int o = wid * 32 + mt * 16 + (lane >> 2);
        bias_lo[mt] = g_bias[o];
        bias_hi[mt] = g_bias[o + 8];
    }

    for (int b = blockIdx.x; b < BTOT; b += gridDim.x) {
        __syncthreads();
        const float* xb = g_xt + (size_t)b * 8192;
        #pragma unroll
        for (int i = 0; i < 32; i++) {
            int idx = t + i * 256;
            int c = idx >> 6, h = idx & 63;
            float v = xb[idx];
            __nv_bfloat16 hi, lo;
            bsplit(v, hi, lo);
            uint32_t off = (uint32_t)h * (LDW * 2) + (uint32_t)c * 2;
            *(__nv_bfloat16*)(smem + SM_XHI + off) = hi;
            *(__nv_bfloat16*)(smem + SM_XLO + off) = lo;
        }
        __syncthreads();

        float acc[2][8][4];
        #pragma unroll
        for (int mt = 0; mt < 2; mt++)
            #pragma unroll
            for (int nt = 0; nt < 8; nt++)
                #pragma unroll
                for (int q = 0; q < 4; q++) acc[mt][nt][q] = 0.f;

        #pragma unroll
        for (int k = 0; k < 8; k++) {
            uint32_t kb = (uint32_t)k * 32;
            uint32_t Ahi[2][4], Alo[2][4], Bhi[4][4], Blo[4][4];
            #pragma unroll
            for (int mt = 0; mt < 2; mt++) {
                uint32_t ao = a_off + (uint32_t)mt * 16 * (LDW * 2) + kb;
                ldsm_x4(Ahi[mt], sb + SM_WHI + ao);
                ldsm_x4(Alo[mt], sb + SM_WLO + ao);
            }
            #pragma unroll
            for (int nt2 = 0; nt2 < 4; nt2++) {
                uint32_t bo = b_off + (uint32_t)nt2 * 16 * (LDW * 2) + kb;
                ldsm_x4(Bhi[nt2], sb + SM_XHI + bo);
                ldsm_x4(Blo[nt2], sb + SM_XLO + bo);
            }
            #pragma unroll
            for (int mt = 0; mt < 2; mt++)
                #pragma unroll
                for (int nt2 = 0; nt2 < 4; nt2++) {
                    mma_bf16(acc[mt][2 * nt2],     Ahi[mt], &Bhi[nt2][0]);
                    mma_bf16(acc[mt][2 * nt2],     Ahi[mt], &Blo[nt2][0]);
                    mma_bf16(acc[mt][2 * nt2],     Alo[mt], &Bhi[nt2][0]);
                    mma_bf16(acc[mt][2 * nt2 + 1], Ahi[mt], &Bhi[nt2][2]);
                    mma_bf16(acc[mt][2 * nt2 + 1], Ahi[mt], &Blo[nt2][2]);
                    mma_bf16(acc[mt][2 * nt2 + 1], Alo[mt], &Bhi[nt2][2]);
                }
        }

        float* op = g_qkv + (size_t)b * 16384;
        #pragma unroll
        for (int mt = 0; mt < 2; mt++) {
            int o = wid * 32 + mt * 16 + (lane >> 2);
            #pragma unroll
            for (int nt = 0; nt < 8; nt++) {
                int h = nt * 8 + 2 * (lane & 3);
                float2 r0, r1;
                r0.x = acc[mt][nt][0] + bias_lo[mt];
                r0.y = acc[mt][nt][1] + bias_lo[mt];
                r1.x = acc[mt][nt][2] + bias_hi[mt];
                r1.y = acc[mt][nt][3] + bias_hi[mt];
                *(float2*)&op[o * 64 + h]       = r0;
                *(float2*)&op[(o + 8) * 64 + h] = r1;
            }
        }
    }
}

// ---------------- attention per (b, g): logits fp32 + PV on HMMA ------------
// dynamic smem layout (bytes):
#define A_OFF_QS   0            // 8*64*4   = 2048   q scaled by aqk
#define A_OFF_KS   2048         // 2048
#define A_OFF_RQ   4096         // 8*128*4  = 4096
#define A_OFF_RK   8192         // 4096
#define A_OFF_L    12288        // 64*68*4  = 17408
#define A_OFF_PHI  29696        // 64*72*2  = 9216   P[i][j] bf16 hi
#define A_OFF_PLO  38912        // 9216
#define A_OFF_PDHI 48128        // 64*136*2 = 17408  PdT[i][d] bf16 hi
#define A_OFF_PDLO 65536        // 17408
#define A_OFF_VHI  82944        // 16*72*2  = 2304   V*ae
#define A_OFF_VLO  85248        // 2304
#define A_OFF_RVHI 87552        // 16*136*2 = 4352   Rv*ao
#define A_OFF_RVLO 91904        // 4352
#define A_OFF_OUT  96256        // 16*68*4  = 4352
#define A_SM_TOTAL 100608

__global__ void __launch_bounds__(256) attn(const float* __restrict__ rel) {
    extern __shared__ __align__(16) char smem[];
    uint32_t sb = smem_u32(smem);
    float* qs = (float*)(smem + A_OFF_QS);
    float* ks = (float*)(smem + A_OFF_KS);
    float* Rq = (float*)(smem + A_OFF_RQ);
    float* Rk = (float*)(smem + A_OFF_RK);
    float* L  = (float*)(smem + A_OFF_L);
    __nv_bfloat16* Phi  = (__nv_bfloat16*)(smem + A_OFF_PHI);
    __nv_bfloat16* Plo  = (__nv_bfloat16*)(smem + A_OFF_PLO);
    __nv_bfloat16* PdHi = (__nv_bfloat16*)(smem + A_OFF_PDHI);
    __nv_bfloat16* PdLo = (__nv_bfloat16*)(smem + A_OFF_PDLO);
    __nv_bfloat16* Vhi  = (__nv_bfloat16*)(smem + A_OFF_VHI);
    __nv_bfloat16* Vlo  = (__nv_bfloat16*)(smem + A_OFF_VLO);
    __nv_bfloat16* Rvhi = (__nv_bfloat16*)(smem + A_OFF_RVHI);
    __nv_bfloat16* Rvlo = (__nv_bfloat16*)(smem + A_OFF_RVLO);
    float* outS = (float*)(smem + A_OFF_OUT);

    int bx = blockIdx.x;
    int g = bx & 7;
    int b = bx >> 3;
    int t = threadIdx.x;

    float aqk = g_aqk[g];
    float rqs = g_aqr[g] / aqk;
    float akr = g_akr[g];

    const float* qkvb = g_qkv + (size_t)b * 16384 + g * 32 * 64;

    // ---- zero PdT (hi+lo contiguous, 34816 B = 2176 float4) ----
    {
        float4* z = (float4*)(smem + A_OFF_PDHI);
        for (int i = t; i < 2176; i += 256) z[i] = make_float4(0.f, 0.f, 0.f, 0.f);
    }
    // ---- stage q,k fp32 ----
    for (int idx = t; idx < 1024; idx += 256) {
        int c = idx >> 6, h = idx & 63;
        float val = qkvb[idx];
        if (c < 8) qs[c * 64 + h] = val * aqk;
        else       ks[(c - 8) * 64 + h] = val;
    }
    // ---- stage V*ae bf16 hi/lo [c][72] ----
    for (int idx = t; idx < 1024; idx += 256) {
        int c = idx >> 6, j = idx & 63;
        float v = qkvb[1024 + idx] * g_ae[g * 16 + c];
        __nv_bfloat16 hi, lo; bsplit(v, hi, lo);
        Vhi[c * 72 + j] = hi;
        Vlo[c * 72 + j] = lo;
    }
    // ---- stage Rq/Rk fp32 (logits phase) ----
    for (int idx = t; idx < 1016; idx += 256) {
        int c = idx / 127, d = idx % 127;
        Rq[c * 128 + d] = rel[c * 127 + d] * rqs;
        Rk[c * 128 + d] = rel[(8 + c) * 127 + d] * akr;
    }
    // ---- stage Rv*ao bf16 hi/lo [c][136], cols >=127 zeroed ----
    for (int idx = t; idx < 2176; idx += 256) {
        int c = idx / 136, d = idx % 136;
        float v = (d < 127) ? rel[(16 + c) * 127 + d] * g_ao[g * 16 + c] : 0.f;
        __nv_bfloat16 hi, lo; bsplit(v, hi, lo);
        Rvhi[c * 136 + d] = hi;
        Rvlo[c * 136 + d] = lo;
    }
    __syncthreads();

    // ---- logits: 4x4 fp32 tile per thread (identical to passing R11) ----
    {
        int ti = t & 15, tj = t >> 4;
        int i0 = ti * 4, j0 = tj * 4;
        int dbase = i0 - j0 + 60;
        int ebase = j0 - i0 + 60;
        float acc[4][4];
        #pragma unroll
        for (int a = 0; a < 4; a++)
            #pragma unroll
            for (int bb = 0; bb < 4; bb++) acc[a][bb] = 0.f;

        #pragma unroll
        for (int c = 0; c < 8; c++) {
            float qv[4], kv[4], rq[7], rk[7];
            #pragma unroll
            for (int ii = 0; ii < 4; ii++) qv[ii] = qs[c * 64 + i0 + ii];
            #pragma unroll
            for (int jj = 0; jj < 4; jj++) kv[jj] = ks[c * 64 + j0 + jj];
            #pragma unroll
            for (int x = 0; x < 7; x++) rq[x] = Rq[c * 128 + dbase + x];
            #pragma unroll
            for (int x = 0; x < 7; x++) rk[x] = Rk[c * 128 + ebase + x];
            #pragma unroll
            for (int ii = 0; ii < 4; ii++)
                #pragma unroll
                for (int jj = 0; jj < 4; jj++)
                    acc[ii][jj] += qv[ii] * (kv[jj] + rq[ii - jj + 3])
                                 + kv[jj] * rk[jj - ii + 3];
        }
        #pragma unroll
        for (int ii = 0; ii < 4; ii++) {
            float4 r;
            r.x = acc[ii][0]; r.y = acc[ii][1]; r.z = acc[ii][2]; r.w = acc[ii][3];
            *(float4*)&L[(i0 + ii) * 68 + j0] = r;
        }
    }
    __syncthreads();

    // ---- softmax -> write P[i][j] and PdT[i][d=i+63-j] bf16 hi/lo ----
    {
        int w = t >> 5, lane = t & 31;
        for (int r = w * 8; r < w * 8 + 8; r++) {
            float x1 = L[r * 68 + lane], x2 = L[r * 68 + 32 + lane];
            float m = fmaxf(x1, x2);
            #pragma unroll
            for (int off = 16; off > 0; off >>= 1)
                m = fmaxf(m, __shfl_xor_sync(0xffffffffu, m, off));
            float e1 = __expf(x1 - m), e2 = __expf(x2 - m);
            float s = e1 + e2;
            #pragma unroll
            for (int off = 16; off > 0; off >>= 1)
                s += __shfl_xor_sync(0xffffffffu, s, off);
            float inv = 1.f / s;
            float p1 = e1 * inv, p2 = e2 * inv;
            __nv_bfloat16 h1, l1, h2, l2;
            bsplit(p1, h1, l1);
            bsplit(p2, h2, l2);
            Phi[r * 72 + lane]       = h1;
            Plo[r * 72 + lane]       = l1;
            Phi[r * 72 + lane + 32]  = h2;
            Plo[r * 72 + lane + 32]  = l2;
            int d1 = r + 63 - lane;         // j = lane
            int d2 = r + 31 - lane;         // j = lane + 32
            PdHi[r * 136 + d1] = h1;
            PdLo[r * 136 + d1] = l1;
            PdHi[r * 136 + d2] = h2;
            PdLo[r * 136 + d2] = l2;
        }
    }
    __syncthreads();

    // ---- PV on HMMA: warp = mb*2 + ntile; C = sv + sve accumulated ----
    {
        int wid = t >> 5, lane = t & 31;
        int mb = wid >> 1, ntile = wid & 1;
        uint32_t a_row  = (uint32_t)(mb * 16 + (lane & 15));
        uint32_t a_coff = ((lane >> 4) << 3) * 2;
        uint32_t aPhi = sb + A_OFF_PHI  + a_row * 144 + a_coff;
        uint32_t aPlo = sb + A_OFF_PLO  + a_row * 144 + a_coff;
        uint32_t aDhi = sb + A_OFF_PDHI + a_row * 272 + a_coff;
        uint32_t aDlo = sb + A_OFF_PDLO + a_row * 272 + a_coff;
        uint32_t b_row  = ((lane >> 4) << 3) + (lane & 7);
        uint32_t b_coff = (((lane >> 3) & 1) << 3) * 2;
        uint32_t bVhi = sb + A_OFF_VHI  + b_row * 144 + b_coff;
        uint32_t bVlo = sb + A_OFF_VLO  + b_row * 144 + b_coff;
        uint32_t bRhi = sb + A_OFF_RVHI + b_row * 272 + b_coff;
        uint32_t bRlo = sb + A_OFF_RVLO + b_row * 272 + b_coff;
        int pair = ntile * 2;

        float acc[4] = {0.f, 0.f, 0.f, 0.f};

        // sv: K = 64 (j), 4 k-steps
        #pragma unroll
        for (int k = 0; k < 4; k++) {
            uint32_t Ah[4], Al[4], Bh[4], Bl[4];
            ldsm_x4(Ah, aPhi + k * 32);
            ldsm_x4(Al, aPlo + k * 32);
            ldsm_x4(Bh, bVhi + k * 32);
            ldsm_x4(Bl, bVlo + k * 32);
            mma_bf16(acc, Ah, &Bh[pair]);
            mma_bf16(acc, Ah, &Bl[pair]);
            mma_bf16(acc, Al, &Bh[pair]);
        }
        // sve: K = 128 (d), nonzero band k-steps mb..mb+4
        #pragma unroll
        for (int kk = 0; kk < 5; kk++) {
            int kd = mb + kk;
            uint32_t Ah[4], Al[4], Bh[4], Bl[4];
            ldsm_x4(Ah, aDhi + kd * 32);
            ldsm_x4(Al, aDlo + kd * 32);
            ldsm_x4(Bh, bRhi + kd * 32);
            ldsm_x4(Bl, bRlo + kd * 32);
            mma_bf16(acc, Ah, &Bh[pair]);
            mma_bf16(acc, Ah, &Bl[pair]);
            mma_bf16(acc, Al, &Bh[pair]);
        }

        // scatter C to outS[c][i] (pad 68 -> conflict-free)
        int cl = ntile * 8 + 2 * (lane & 3);
        int il = mb * 16 + (lane >> 2);
        outS[cl * 68 + il]           = acc[0];
        outS[(cl + 1) * 68 + il]     = acc[1];
        outS[cl * 68 + il + 8]       = acc[2];
        outS[(cl + 1) * 68 + il + 8] = acc[3];
    }
    __syncthreads();

    // ---- coalesced copy-out with bias ----
    for (int idx = t; idx < 1024; idx += 256) {
        int c = idx >> 6, i = idx & 63;
        g_att[(size_t)b * 8192 + (g * 16 + c) * 64 + i]
            = outS[c * 68 + i] + g_bs[g * 16 + c];
    }
}

// ---------------- final transpose ----------------
__global__ void tr_out(float* __restrict__ out) {
    __shared__ float tile[32][33];
    int n = blockIdx.z;
    int q0 = blockIdx.y * 32;
    int w0 = blockIdx.x * 32;
    #pragma unroll
    for (int y = threadIdx.y; y < 32; y += 8)
        tile[y][threadIdx.x] =
            g_att[(size_t)(n * 64 + w0 + y) * 8192 + q0 + threadIdx.x];
    __syncthreads();
    #pragma unroll
    for (int y = threadIdx.y; y < 32; y += 8)
        out[(size_t)n * 524288 + (size_t)(q0 + y) * 64 + w0 + threadIdx.x]
            = tile[threadIdx.x][y];
}

// ---------------- launch ----------------
extern "C" void kernel_launch(void* const* d_in, const int* in_sizes, int n_in,
                              void* d_out, int out_size) {
    const float* x    = (const float*)d_in[0];
    const float* wqkv = (const float*)d_in[1];
    const float* rel  = (const float*)d_in[2];
    const float* bnq  = (const float*)d_in[3];
    const float* bns  = (const float*)d_in[4];
    const float* bno  = (const float*)d_in[5];
    float* out = (float*)d_out;

    cudaFuncSetAttribute(qkv_mma, cudaFuncAttributeMaxDynamicSharedMemorySize, SM_TOTAL);
    cudaFuncSetAttribute(attn, cudaFuncAttributeMaxDynamicSharedMemorySize, A_SM_TOTAL);

    prep_params<<<1, 256>>>(bnq, bns, bno);
    prep_wsplit<<<256, 128>>>(wqkv);
    tr_x<<<dim3(2, 2, 2048), dim3(32, 8)>>>(x);
    qkv_mma<<<148, 256, SM_TOTAL>>>();
    attn<<<8192, 256, A_SM_TOTAL>>>(rel);
    tr_out<<<dim3(2, 256, 16), dim3(32, 8)>>>(out);
}

// round 13
// speedup vs baseline: 1.1957x; 1.1957x over previous
#include <cuda_runtime.h>
#include <cuda_bf16.h>
#include <cstdint>

// Problem constants
#define NIMG 16
#define CIN 128
#define HDIM 64
#define WDIM 64
#define BTOT (NIMG*WDIM)      // 1024
#define OQKV 256
#define NGROUP 8
#define BNEPS 1e-5f

// ---------------- scratch ----------------
__device__ __align__(16) float g_xt [BTOT * CIN * HDIM];     // [b][c][h]
__device__ __align__(16) float g_qkv[BTOT * OQKV * HDIM];    // [b][o][h]
__device__ __align__(16) float g_att[BTOT * 128 * HDIM];     // [b][p][h]
__device__ __align__(16) __nv_bfloat16 g_whi[OQKV * CIN];
__device__ __align__(16) __nv_bfloat16 g_wlo[OQKV * CIN];
__device__ float g_bias[OQKV];
__device__ float g_sc  [OQKV];
__device__ float g_aqk[NGROUP], g_aqr[NGROUP], g_akr[NGROUP];
__device__ float g_ae[128], g_ao[128], g_bs[128];

// ---------------- mma.sync helpers (sm_80+ PTX) ------------------------------
__device__ __forceinline__ uint32_t smem_u32(const void* p) {
    uint32_t a;
    asm("{ .reg .u64 t; cvta.to.shared.u64 t, %1; cvt.u32.u64 %0, t; }" : "=r"(a) : "l"(p));
    return a;
}
__device__ __forceinline__ void ldsm_x4(uint32_t* r, uint32_t addr) {
    asm volatile("ldmatrix.sync.aligned.m8n8.x4.shared.b16 {%0,%1,%2,%3}, [%4];"
                 : "=r"(r[0]), "=r"(r[1]), "=r"(r[2]), "=r"(r[3]) : "r"(addr));
}
__device__ __forceinline__ void mma_bf16(float* c, const uint32_t* a, const uint32_t* b) {
    asm volatile("mma.sync.aligned.m16n8k16.row.col.f32.bf16.bf16.f32 "
                 "{%0,%1,%2,%3}, {%4,%5,%6,%7}, {%8,%9}, {%0,%1,%2,%3};"
                 : "+f"(c[0]), "+f"(c[1]), "+f"(c[2]), "+f"(c[3])
                 : "r"(a[0]), "r"(a[1]), "r"(a[2]), "r"(a[3]), "r"(b[0]), "r"(b[1]));
}
__device__ __forceinline__ void bsplit(float v, __nv_bfloat16& hi, __nv_bfloat16& lo) {
    hi = __float2bfloat16_rn(v);
    lo = __float2bfloat16_rn(v - __bfloat162float(hi));
}

// ---------------- prep ----------------
__global__ void prep_params(const float* __restrict__ bnq,
                            const float* __restrict__ bns,
                            const float* __restrict__ bno) {
    int t = threadIdx.x;
    if (t < 256) {
        float ga = bnq[t], be = bnq[256 + t], m = bnq[512 + t], v = bnq[768 + t];
        float s = ga * rsqrtf(v + BNEPS);
        g_sc[t]  = s;
        g_bias[t] = be - s * m;
    }
    if (t < 24) {
        float s = bns[t] * rsqrtf(bns[72 + t] + BNEPS);
        if (t < 8)       g_aqk[t]      = s;
        else if (t < 16) g_aqr[t - 8]  = s;
        else             g_akr[t - 16] = s;
    }
    if (t < 128) {
        int c0 = 2 * t, c1 = 2 * t + 1;
        float s0 = bno[c0] * rsqrtf(bno[768 + c0] + BNEPS);
        float s1 = bno[c1] * rsqrtf(bno[768 + c1] + BNEPS);
        g_ae[t] = s0;
        g_ao[t] = s1;
        g_bs[t] = (bno[256 + c0] - s0 * bno[512 + c0])
                + (bno[256 + c1] - s1 * bno[512 + c1]);
    }
}

__global__ void prep_wsplit(const float* __restrict__ w) {
    int o = blockIdx.x, k = threadIdx.x;
    float we = w[o * 128 + k] * g_sc[o];
    __nv_bfloat16 hi, lo;
    bsplit(we, hi, lo);
    g_whi[o * 128 + k] = hi;
    g_wlo[o * 128 + k] = lo;
}

// ---------------- transpose x ----------------
__global__ void tr_x(const float* __restrict__ x) {
    __shared__ float tile[32][33];
    int nc = blockIdx.z;
    int n = nc >> 7, c = nc & 127;
    int h0 = blockIdx.x * 32, w0 = blockIdx.y * 32;
    const float* src = x + ((size_t)(n * 128 + c)) * 4096;
    #pragma unroll
    for (int y = threadIdx.y; y < 32; y += 8)
        tile[y][threadIdx.x] = src[(h0 + y) * 64 + w0 + threadIdx.x];
    __syncthreads();
    #pragma unroll
    for (int y = threadIdx.y; y < 32; y += 8)
        g_xt[((size_t)((n * 64 + (w0 + y)) * 128 + c)) * 64 + h0 + threadIdx.x]
            = tile[threadIdx.x][y];
}

// ---------------- QKV GEMM (unchanged from R11 pass) ----------------
#define LDW 136
#define SM_WHI 0
#define SM_WLO (SM_WHI + OQKV * LDW * 2)
#define SM_XHI (SM_WLO + OQKV * LDW * 2)
#define SM_XLO (SM_XHI + HDIM * LDW * 2)
#define SM_TOTAL (SM_XLO + HDIM * LDW * 2)

__global__ void __launch_bounds__(256, 1) qkv_mma() {
    extern __shared__ __align__(16) char smem[];
    uint32_t sb = smem_u32(smem);
    int t = threadIdx.x;
    int wid = t >> 5, lane = t & 31;

    {
        const float4* whi = (const float4*)g_whi;
        const float4* wlo = (const float4*)g_wlo;
        #pragma unroll
        for (int i = 0; i < 16; i++) {
            int idx = t + i * 256;
            int o = idx >> 4, c4 = idx & 15;
            *(float4*)(smem + SM_WHI + o * (LDW * 2) + c4 * 16) = whi[idx];
            *(float4*)(smem + SM_WLO + o * (LDW * 2) + c4 * 16) = wlo[idx];
        }
    }

    uint32_t a_row = (uint32_t)(wid * 32) + (lane & 15);
    uint32_t a_off = a_row * (LDW * 2) + ((lane >> 4) << 3) * 2;
    uint32_t b_row = ((lane >> 4) << 3) + (lane & 7);
    uint32_t b_off = b_row * (LDW * 2) + (((lane >> 3) & 1) << 3) * 2;

    float bias_lo[2], bias_hi[2];
    #pragma unroll
    for (int mt = 0; mt < 2; mt++) {
        int o = wid * 32 + mt * 16 + (lane >> 2);
        bias_lo[mt] = g_bias[o];
        bias_hi[mt] = g_bias[o + 8];
    }

    for (int b = blockIdx.x; b < BTOT; b += gridDim.x) {
        __syncthreads();
        const float* xb = g_xt + (size_t)b * 8192;
        #pragma unroll
        for (int i = 0; i < 32; i++) {
            int idx = t + i * 256;
            int c = idx >> 6, h = idx & 63;
            float v = xb[idx];
            __nv_bfloat16 hi, lo;
            bsplit(v, hi, lo);
            uint32_t off = (uint32_t)h * (LDW * 2) + (uint32_t)c * 2;
            *(__nv_bfloat16*)(smem + SM_XHI + off) = hi;
            *(__nv_bfloat16*)(smem + SM_XLO + off) = lo;
        }
        __syncthreads();

        float acc[2][8][4];
        #pragma unroll
        for (int mt = 0; mt < 2; mt++)
            #pragma unroll
            for (int nt = 0; nt < 8; nt++)
                #pragma unroll
                for (int q = 0; q < 4; q++) acc[mt][nt][q] = 0.f;

        #pragma unroll
        for (int k = 0; k < 8; k++) {
            uint32_t kb = (uint32_t)k * 32;
            uint32_t Ahi[2][4], Alo[2][4], Bhi[4][4], Blo[4][4];
            #pragma unroll
            for (int mt = 0; mt < 2; mt++) {
                uint32_t ao = a_off + (uint32_t)mt * 16 * (LDW * 2) + kb;
                ldsm_x4(Ahi[mt], sb + SM_WHI + ao);
                ldsm_x4(Alo[mt], sb + SM_WLO + ao);
            }
            #pragma unroll
            for (int nt2 = 0; nt2 < 4; nt2++) {
                uint32_t bo = b_off + (uint32_t)nt2 * 16 * (LDW * 2) + kb;
                ldsm_x4(Bhi[nt2], sb + SM_XHI + bo);
                ldsm_x4(Blo[nt2], sb + SM_XLO + bo);
            }
            #pragma unroll
            for (int mt = 0; mt < 2; mt++)
                #pragma unroll
                for (int nt2 = 0; nt2 < 4; nt2++) {
                    mma_bf16(acc[mt][2 * nt2],     Ahi[mt], &Bhi[nt2][0]);
                    mma_bf16(acc[mt][2 * nt2],     Ahi[mt], &Blo[nt2][0]);
                    mma_bf16(acc[mt][2 * nt2],     Alo[mt], &Bhi[nt2][0]);
                    mma_bf16(acc[mt][2 * nt2 + 1], Ahi[mt], &Bhi[nt2][2]);
                    mma_bf16(acc[mt][2 * nt2 + 1], Ahi[mt], &Blo[nt2][2]);
                    mma_bf16(acc[mt][2 * nt2 + 1], Alo[mt], &Bhi[nt2][2]);
                }
        }

        float* op = g_qkv + (size_t)b * 16384;
        #pragma unroll
        for (int mt = 0; mt < 2; mt++) {
            int o = wid * 32 + mt * 16 + (lane >> 2);
            #pragma unroll
            for (int nt = 0; nt < 8; nt++) {
                int h = nt * 8 + 2 * (lane & 3);
                float2 r0, r1;
                r0.x = acc[mt][nt][0] + bias_lo[mt];
                r0.y = acc[mt][nt][1] + bias_lo[mt];
                r1.x = acc[mt][nt][2] + bias_hi[mt];
                r1.y = acc[mt][nt][3] + bias_hi[mt];
                *(float2*)&op[o * 64 + h]       = r0;
                *(float2*)&op[(o + 8) * 64 + h] = r1;
            }
        }
    }
}

// ---------------- attention: compact 64KB layout, PV on HMMA ----------------
// byte offsets (overlays documented):
#define A_OFF_QS   0            // 2048  qs fp32       [dead after logits; outS overlays]
#define A_OFF_KS   2048         // 2048  ks
#define A_OFF_RQ   4096         // 4096  Rq
#define A_OFF_RK   8192         // 4096  Rk
#define A_OFF_L    12288        // 17408 L fp32 (64 rows x 272 B)
                                //      post-softmax: row i = Phi[i] (144 B) + Plo[i] (128 B)
#define A_OFF_PDB  29696        // 11264 PdbHi banded 64x88 bf16 (stride 176)
#define A_OFF_PDBL 40960        // 11264 PdbLo
#define A_OFF_V    52224        // 2304  Vhi 16x72 (stride 144)
#define A_OFF_VLO  54528        // 2304  Vlo
#define A_OFF_RV   56832        // 4352  Rvhi 16x136 (stride 272)
#define A_OFF_RVLO 61184        // 4352  Rvlo
#define A_SM_TOTAL 65536
#define A_OFF_OUT  0            // outS fp32 16x68 (4352) overlays qs/ks post-logits

__global__ void __launch_bounds__(256) attn(const float* __restrict__ rel) {
    extern __shared__ __align__(16) char smem[];
    uint32_t sb = smem_u32(smem);
    float* qs = (float*)(smem + A_OFF_QS);
    float* ks = (float*)(smem + A_OFF_KS);
    float* Rq = (float*)(smem + A_OFF_RQ);
    float* Rk = (float*)(smem + A_OFF_RK);
    float* L  = (float*)(smem + A_OFF_L);
    __nv_bfloat16* Vhi  = (__nv_bfloat16*)(smem + A_OFF_V);
    __nv_bfloat16* Vlo  = (__nv_bfloat16*)(smem + A_OFF_VLO);
    __nv_bfloat16* Rvhi = (__nv_bfloat16*)(smem + A_OFF_RV);
    __nv_bfloat16* Rvlo = (__nv_bfloat16*)(smem + A_OFF_RVLO);
    float* outS = (float*)(smem + A_OFF_OUT);

    int bx = blockIdx.x;
    int g = bx & 7;
    int b = bx >> 3;
    int t = threadIdx.x;

    float aqk = g_aqk[g];
    float rqs = g_aqr[g] / aqk;
    float akr = g_akr[g];

    const float* qkvb = g_qkv + (size_t)b * 16384 + g * 32 * 64;

    // ---- stage ----
    for (int idx = t; idx < 1024; idx += 256) {
        int c = idx >> 6, h = idx & 63;
        float val = qkvb[idx];
        if (c < 8) qs[c * 64 + h] = val * aqk;
        else       ks[(c - 8) * 64 + h] = val;
    }
    for (int idx = t; idx < 1024; idx += 256) {
        int c = idx >> 6, j = idx & 63;
        float v = qkvb[1024 + idx] * g_ae[g * 16 + c];
        __nv_bfloat16 hi, lo; bsplit(v, hi, lo);
        Vhi[c * 72 + j] = hi;
        Vlo[c * 72 + j] = lo;
    }
    for (int idx = t; idx < 1016; idx += 256) {
        int c = idx / 127, d = idx % 127;
        Rq[c * 128 + d] = rel[c * 127 + d] * rqs;
        Rk[c * 128 + d] = rel[(8 + c) * 127 + d] * akr;
    }
    for (int idx = t; idx < 2176; idx += 256) {
        int c = idx / 136, d = idx % 136;
        float v = (d < 127) ? rel[(16 + c) * 127 + d] * g_ao[g * 16 + c] : 0.f;
        __nv_bfloat16 hi, lo; bsplit(v, hi, lo);
        Rvhi[c * 136 + d] = hi;
        Rvlo[c * 136 + d] = lo;
    }
    __syncthreads();

    // ---- logits: 4x4 fp32 tile per thread (proven) ----
    {
        int ti = t & 15, tj = t >> 4;
        int i0 = ti * 4, j0 = tj * 4;
        int dbase = i0 - j0 + 60;
        int ebase = j0 - i0 + 60;
        float acc[4][4];
        #pragma unroll
        for (int a = 0; a < 4; a++)
            #pragma unroll
            for (int bb = 0; bb < 4; bb++) acc[a][bb] = 0.f;

        #pragma unroll
        for (int c = 0; c < 8; c++) {
            float qv[4], kv[4], rq[7], rk[7];
            #pragma unroll
            for (int ii = 0; ii < 4; ii++) qv[ii] = qs[c * 64 + i0 + ii];
            #pragma unroll
            for (int jj = 0; jj < 4; jj++) kv[jj] = ks[c * 64 + j0 + jj];
            #pragma unroll
            for (int x = 0; x < 7; x++) rq[x] = Rq[c * 128 + dbase + x];
            #pragma unroll
            for (int x = 0; x < 7; x++) rk[x] = Rk[c * 128 + ebase + x];
            #pragma unroll
            for (int ii = 0; ii < 4; ii++)
                #pragma unroll
                for (int jj = 0; jj < 4; jj++)
                    acc[ii][jj] += qv[ii] * (kv[jj] + rq[ii - jj + 3])
                                 + kv[jj] * rk[jj - ii + 3];
        }
        #pragma unroll
        for (int ii = 0; ii < 4; ii++) {
            float4 r;
            r.x = acc[ii][0]; r.y = acc[ii][1]; r.z = acc[ii][2]; r.w = acc[ii][3];
            *(float4*)&L[(i0 + ii) * 68 + j0] = r;
        }
    }
    __syncthreads();

    // ---- softmax: in-place P (over L row) + banded PdT ----
    {
        int w = t >> 5, lane = t & 31;
        for (int r = w * 8; r < w * 8 + 8; r++) {
            float x1 = L[r * 68 + lane], x2 = L[r * 68 + 32 + lane];
            float m = fmaxf(x1, x2);
            #pragma unroll
            for (int off = 16; off > 0; off >>= 1)
                m = fmaxf(m, __shfl_xor_sync(0xffffffffu, m, off));
            float e1 = __expf(x1 - m), e2 = __expf(x2 - m);
            float s = e1 + e2;
            #pragma unroll
            for (int off = 16; off > 0; off >>= 1)
                s += __shfl_xor_sync(0xffffffffu, s, off);
            // all lanes' L-row reads complete before the shfl syncs above;
            // in-place overwrite below is therefore safe under ITS.
            float inv = 1.f / s;
            float p1 = e1 * inv, p2 = e2 * inv;
            __nv_bfloat16 h1, l1, h2, l2;
            bsplit(p1, h1, l1);
            bsplit(p2, h2, l2);
            __nv_bfloat16* rowH = (__nv_bfloat16*)(smem + A_OFF_L + r * 272);
            __nv_bfloat16* rowL = (__nv_bfloat16*)(smem + A_OFF_L + r * 272 + 144);
            rowH[lane]      = h1;
            rowH[lane + 32] = h2;
            rowL[lane]      = l1;
            rowL[lane + 32] = l2;
            // banded PdT: zero row (44 words each hi/lo), then scatter
            uint32_t* zh = (uint32_t*)(smem + A_OFF_PDB  + r * 176);
            uint32_t* zl = (uint32_t*)(smem + A_OFF_PDBL + r * 176);
            zh[lane] = 0; zl[lane] = 0;
            if (lane < 12) { zh[32 + lane] = 0; zl[32 + lane] = 0; }
            __syncwarp();
            int mb16 = (r >> 4) << 4;
            int d1 = r + 63 - lane - mb16;      // j = lane
            int d2 = r + 31 - lane - mb16;      // j = lane + 32
            __nv_bfloat16* ph = (__nv_bfloat16*)(smem + A_OFF_PDB  + r * 176);
            __nv_bfloat16* pl = (__nv_bfloat16*)(smem + A_OFF_PDBL + r * 176);
            ph[d1] = h1; pl[d1] = l1;
            ph[d2] = h2; pl[d2] = l2;
        }
    }
    __syncthreads();

    // ---- PV on HMMA: warp = mb*2 + ntile; C = sv + sve accumulated ----
    {
        int wid = t >> 5, lane = t & 31;
        int mb = wid >> 1, ntile = wid & 1;
        uint32_t a_row  = (uint32_t)(mb * 16 + (lane & 15));
        uint32_t a_coff = ((lane >> 4) << 3) * 2;
        uint32_t aPhi = sb + A_OFF_L    + a_row * 272 + a_coff;
        uint32_t aPlo = sb + A_OFF_L    + a_row * 272 + 144 + a_coff;
        uint32_t aDhi = sb + A_OFF_PDB  + a_row * 176 + a_coff;
        uint32_t aDlo = sb + A_OFF_PDBL + a_row * 176 + a_coff;
        uint32_t b_row  = ((lane >> 4) << 3) + (lane & 7);
        uint32_t b_coff = (((lane >> 3) & 1) << 3) * 2;
        uint32_t bVhi = sb + A_OFF_V    + b_row * 144 + b_coff;
        uint32_t bVlo = sb + A_OFF_VLO  + b_row * 144 + b_coff;
        uint32_t bRhi = sb + A_OFF_RV   + b_row * 272 + b_coff;
        uint32_t bRlo = sb + A_OFF_RVLO + b_row * 272 + b_coff;
        int pair = ntile * 2;

        float acc[4] = {0.f, 0.f, 0.f, 0.f};

        // sv: K = 64 (j), 4 k-steps
        #pragma unroll
        for (int k = 0; k < 4; k++) {
            uint32_t Ah[4], Al[4], Bh[4], Bl[4];
            ldsm_x4(Ah, aPhi + k * 32);
            ldsm_x4(Al, aPlo + k * 32);
            ldsm_x4(Bh, bVhi + k * 32);
            ldsm_x4(Bl, bVlo + k * 32);
            mma_bf16(acc, Ah, &Bh[pair]);
            mma_bf16(acc, Ah, &Bl[pair]);
            mma_bf16(acc, Al, &Bh[pair]);
        }
        // sve: banded K; A k-steps 0..4 (d'=d-16mb), B at absolute d = 16(mb+kk)
        #pragma unroll
        for (int kk = 0; kk < 5; kk++) {
            uint32_t Ah[4], Al[4], Bh[4], Bl[4];
            ldsm_x4(Ah, aDhi + kk * 32);
            ldsm_x4(Al, aDlo + kk * 32);
            ldsm_x4(Bh, bRhi + (mb + kk) * 32);
            ldsm_x4(Bl, bRlo + (mb + kk) * 32);
            mma_bf16(acc, Ah, &Bh[pair]);
            mma_bf16(acc, Ah, &Bl[pair]);
            mma_bf16(acc, Al, &Bh[pair]);
        }

        // scatter C to outS[c][i]
        int cl = ntile * 8 + 2 * (lane & 3);
        int il = mb * 16 + (lane >> 2);
        outS[cl * 68 + il]           = acc[0];
        outS[(cl + 1) * 68 + il]     = acc[1];
        outS[cl * 68 + il + 8]       = acc[2];
        outS[(cl + 1) * 68 + il + 8] = acc[3];
    }
    __syncthreads();

    // ---- coalesced copy-out with bias ----
    for (int idx = t; idx < 1024; idx += 256) {
        int c = idx >> 6, i = idx & 63;
        g_att[(size_t)b * 8192 + (g * 16 + c) * 64 + i]
            = outS[c * 68 + i] + g_bs[g * 16 + c];
    }
}

// ---------------- final transpose ----------------
__global__ void tr_out(float* __restrict__ out) {
    __shared__ float tile[32][33];
    int n = blockIdx.z;
    int q0 = blockIdx.y * 32;
    int w0 = blockIdx.x * 32;
    #pragma unroll
    for (int y = threadIdx.y; y < 32; y += 8)
        tile[y][threadIdx.x] =
            g_att[(size_t)(n * 64 + w0 + y) * 8192 + q0 + threadIdx.x];
    __syncthreads();
    #pragma unroll
    for (int y = threadIdx.y; y < 32; y += 8)
        out[(size_t)n * 524288 + (size_t)(q0 + y) * 64 + w0 + threadIdx.x]
            = tile[threadIdx.x][y];
}

// ---------------- launch ----------------
extern "C" void kernel_launch(void* const* d_in, const int* in_sizes, int n_in,
                              void* d_out, int out_size) {
    const float* x    = (const float*)d_in[0];
    const float* wqkv = (const float*)d_in[1];
    const float* rel  = (const float*)d_in[2];
    const float* bnq  = (const float*)d_in[3];
    const float* bns  = (const float*)d_in[4];
    const float* bno  = (const float*)d_in[5];
    float* out = (float*)d_out;

    cudaFuncSetAttribute(qkv_mma, cudaFuncAttributeMaxDynamicSharedMemorySize, SM_TOTAL);
    cudaFuncSetAttribute(attn, cudaFuncAttributeMaxDynamicSharedMemorySize, A_SM_TOTAL);

    prep_params<<<1, 256>>>(bnq, bns, bno);
    prep_wsplit<<<256, 128>>>(wqkv);
    tr_x<<<dim3(2, 2, 2048), dim3(32, 8)>>>(x);
    qkv_mma<<<148, 256, SM_TOTAL>>>();
    attn<<<8192, 256, A_SM_TOTAL>>>(rel);
    tr_out<<<dim3(2, 256, 16), dim3(32, 8)>>>(out);
}